// round 8
// baseline (speedup 1.0000x reference)
#include <cuda_runtime.h>

// ---------------- problem constants ----------------
#define NN     20000        // nodes
#define E0     320000       // input edges
#define EA     340000       // edges + self loops
#define NG     512          // graphs
#define H1     10           // heads layer 1
#define C1     78           // per-head channels layer 1
#define F0     78           // input features
#define F1     780          // H1*C1
#define C2     100          // layer-2 channels
#define SLOPE  0.2f

// ---------------- device scratch (static; no runtime allocation) ----------------
__device__ int   g_is32;
__device__ int   g_src[EA];
__device__ int   g_dst[EA];
__device__ int   g_ssrc[EA];          // src permuted into dst-sorted order (CSR)
__device__ int   g_cnt[NN];
__device__ int   g_cur[NN];
__device__ int   g_off[NN + 1];
__device__ int   g_batch[NN];
__device__ float g_h1[NN * F1];       // 62 MB
__device__ float g_as1[NN * H1];
__device__ float g_ad1[NN * H1];
__device__ float g_out1[NN * F1];     // 62 MB (post bias+ELU)
__device__ float g_h2[NN * C2];
__device__ float g_as2[NN];
__device__ float g_ad2[NN];
__device__ float g_gmax[NG * C2];

// float atomic max via sign-aware integer ops (monotone in float order).
__device__ __forceinline__ void atomicMaxF(float* a, float v) {
    if (v >= 0.0f) atomicMax((int*)a, __float_as_int(v));
    else           atomicMin((unsigned int*)a, __float_as_uint(v));
}

// ---------------- prep: init + int-width detect fused ----------------
__global__ void k_prep(const unsigned int* __restrict__ buf) {
    int i = blockIdx.x * blockDim.x + threadIdx.x;
    int stride = gridDim.x * blockDim.x;
    for (int j = i; j < NN; j += stride) { g_cnt[j] = 0; g_cur[j] = 0; }
    for (int j = i; j < NG * C2; j += stride) g_gmax[j] = 0.0f; // pooled vals post-ReLU >= 0
    if (i == 0) g_is32 = 0;
    int found = 0;
    for (int j = 2 * i + 1; j < 2 * E0; j += 2 * stride) found |= (buf[j] != 0u);
    if (found) atomicOr(&g_is32, 1);   // benign race with init (0 -> or 1)
}

// convert + histogram fused
__global__ void k_convert(const int* __restrict__ eidx, const int* __restrict__ bin) {
    int i = blockIdx.x * blockDim.x + threadIdx.x;
    int stride = gridDim.x * blockDim.x;
    int is32 = g_is32;
    for (int e = i; e < EA; e += stride) {
        int s, d;
        if (e < E0) {
            if (is32) { s = eidx[e];     d = eidx[E0 + e]; }
            else      { s = eidx[2 * e]; d = eidx[2 * E0 + 2 * e]; }
        } else { s = e - E0; d = s; }   // self loop
        g_src[e] = s; g_dst[e] = d;
        atomicAdd(&g_cnt[d], 1);
    }
    for (int n = i; n < NN; n += stride)
        g_batch[n] = is32 ? bin[n] : bin[2 * n];
}

// ---------------- single-pass scan: 1024 threads x 20 elements (int4 loads) ----------------
#define SPER 20   // 1024 * 20 = 20480 >= NN+1
__global__ void k_scan() {
    int t = threadIdx.x;
    int base = t * SPER;                         // 80-byte aligned
    int raw[SPER];
#pragma unroll
    for (int q = 0; q < SPER / 4; q++) {
        int4 v4 = make_int4(0, 0, 0, 0);
        if (base + q * 4 + 3 < NN) v4 = *(const int4*)&g_cnt[base + q * 4];
        else {
#pragma unroll
            for (int r = 0; r < 4; r++) {
                int idx = base + q * 4 + r;
                ((int*)&v4)[r] = (idx < NN) ? g_cnt[idx] : 0;
            }
        }
        raw[q * 4 + 0] = v4.x; raw[q * 4 + 1] = v4.y;
        raw[q * 4 + 2] = v4.z; raw[q * 4 + 3] = v4.w;
    }
    int vals[SPER];
    int sum = 0;
#pragma unroll
    for (int i = 0; i < SPER; i++) { vals[i] = sum; sum += raw[i]; }
    __shared__ int wsum[32];
    int x = sum;
#pragma unroll
    for (int o = 1; o < 32; o <<= 1) {
        int y = __shfl_up_sync(0xffffffffu, x, o);
        if ((t & 31) >= o) x += y;
    }
    if ((t & 31) == 31) wsum[t >> 5] = x;
    __syncthreads();
    if (t < 32) {
        int w = wsum[t];
#pragma unroll
        for (int o = 1; o < 32; o <<= 1) {
            int y = __shfl_up_sync(0xffffffffu, w, o);
            if (t >= o) w += y;
        }
        wsum[t] = w;
    }
    __syncthreads();
    int prev = (x - sum) + ((t >= 32) ? wsum[(t >> 5) - 1] : 0);
#pragma unroll
    for (int i = 0; i < SPER; i++) {
        int idx = base + i;
        if (idx <= NN) g_off[idx] = prev + vals[i];
    }
}

__global__ void k_scatter() {
    int i = blockIdx.x * blockDim.x + threadIdx.x;
    int stride = gridDim.x * blockDim.x;
    for (int e = i; e < EA; e += stride) {
        int d = g_dst[e];
        int pos = g_off[d] + atomicAdd(&g_cur[d], 1);
        g_ssrc[pos] = g_src[e];
    }
}

// ---------------- GEMM1: h1 = x @ W1, 128 outs x 64 nodes, prefetch pipeline ----------------
#define G1ON 128
#define G1NN 64
#define G1PAD 68     // padded node stride (16B-aligned)
__global__ void __launch_bounds__(256) k_gemm1(const float* __restrict__ x,
                                               const float* __restrict__ W1) {
    __shared__ float xs[F0 * G1PAD];             // 21.2 KB, layout [k][node]
    int tid = threadIdx.x;                       // 256
    int n0  = blockIdx.y * G1NN;
    int ob  = blockIdx.x * G1ON + (tid & 31) * 4;
    int nb  = (tid >> 5) * 8;
    for (int i = tid; i < G1NN * F0; i += 256) {
        int nn = i / F0, k = i - nn * F0;
        int node = n0 + nn;
        xs[k * G1PAD + nn] = (node < NN) ? x[(size_t)node * F0 + k] : 0.0f;
    }
    __syncthreads();
    float acc[8][4];
#pragma unroll
    for (int n = 0; n < 8; n++)
#pragma unroll
        for (int q = 0; q < 4; q++) acc[n][q] = 0.0f;
    if (ob < F1) {
        float4 w  = *(const float4*)&W1[ob];
        float4 xa = *(const float4*)&xs[nb];
        float4 xb = *(const float4*)&xs[nb + 4];
        for (int k = 0; k < F0; k++) {
            float4 wc = w, xac = xa, xbc = xb;
            if (k + 1 < F0) {                      // prefetch k+1
                w  = *(const float4*)&W1[(k + 1) * F1 + ob];
                xa = *(const float4*)&xs[(k + 1) * G1PAD + nb];
                xb = *(const float4*)&xs[(k + 1) * G1PAD + nb + 4];
            }
            float xv[8] = {xac.x, xac.y, xac.z, xac.w, xbc.x, xbc.y, xbc.z, xbc.w};
#pragma unroll
            for (int n = 0; n < 8; n++) {
                acc[n][0] = fmaf(xv[n], wc.x, acc[n][0]);
                acc[n][1] = fmaf(xv[n], wc.y, acc[n][1]);
                acc[n][2] = fmaf(xv[n], wc.z, acc[n][2]);
                acc[n][3] = fmaf(xv[n], wc.w, acc[n][3]);
            }
        }
#pragma unroll
        for (int n = 0; n < 8; n++) {
            int node = n0 + nb + n;
            if (node < NN)
                *(float4*)&g_h1[(size_t)node * F1 + ob] =
                    make_float4(acc[n][0], acc[n][1], acc[n][2], acc[n][3]);
        }
    }
}

// alpha_{s,d}1[n][h] = dot(h1[n, h*C1:], a_{src,dst}1[h]) — one warp per (n,h)
__global__ void k_alpha1(const float* __restrict__ as, const float* __restrict__ ad) {
    int gw   = (blockIdx.x * blockDim.x + threadIdx.x) >> 5;
    int lane = threadIdx.x & 31;
    if (gw < NN * H1) {
        int n = gw / H1, h = gw - n * H1;
        const float* hp = g_h1 + (size_t)n * F1 + h * C1;
        float s = 0.0f, d = 0.0f;
        for (int k = lane; k < C1; k += 32) {
            float v = hp[k];
            s = fmaf(v, as[h * C1 + k], s);
            d = fmaf(v, ad[h * C1 + k], d);
        }
#pragma unroll
        for (int off = 16; off; off >>= 1) {
            s += __shfl_down_sync(0xffffffffu, s, off);
            d += __shfl_down_sync(0xffffffffu, d, off);
        }
        if (lane == 0) { g_as1[gw] = s; g_ad1[gw] = d; }
    }
}

// ---------------- layer-1 fused softmax + aggregation (one block per dst) ----------------
#define CH1   32
#define NV1   195        // F1/4 float4 lanes
#define EVCAP 128        // cached-logit capacity (deg ~ Poisson(17))
__global__ void k_agg1(const float* __restrict__ b1) {
    int d = blockIdx.x;
    int t = threadIdx.x;                      // 256
    __shared__ float smax[H1], sden[H1], sad[H1], srr[H1];
    __shared__ int   csrc[CH1];
    __shared__ float cal[CH1][H1];
    __shared__ float ev[EVCAP][H1];
    if (t < H1) {
        smax[t] = __int_as_float(0xff800000); // -inf
        sden[t] = 0.0f;
        sad[t]  = g_ad1[d * H1 + t];
    }
    __syncthreads();
    int off = g_off[d], deg = g_off[d + 1] - off;
    int n = deg * H1;
    bool cached = (deg <= EVCAP);
    if (cached) {
        for (int i = t; i < n; i += 256) {
            int j = i / H1, h = i - H1 * j;
            int s = g_ssrc[off + j];
            float v = g_as1[s * H1 + h] + sad[h];
            v = v > 0.0f ? v : SLOPE * v;
            ev[j][h] = v;
            atomicMaxF(&smax[h], v);
        }
        __syncthreads();
        for (int i = t; i < n; i += 256) {
            int j = i / H1, h = i - H1 * j;
            atomicAdd(&sden[h], __expf(ev[j][h] - smax[h]));
        }
    } else {
        for (int i = t; i < n; i += 256) {
            int j = i / H1, h = i - H1 * j;
            int s = g_ssrc[off + j];
            float v = g_as1[s * H1 + h] + sad[h];
            v = v > 0.0f ? v : SLOPE * v;
            atomicMaxF(&smax[h], v);
        }
        __syncthreads();
        for (int i = t; i < n; i += 256) {
            int j = i / H1, h = i - H1 * j;
            int s = g_ssrc[off + j];
            float v = g_as1[s * H1 + h] + sad[h];
            v = v > 0.0f ? v : SLOPE * v;
            atomicAdd(&sden[h], __expf(v - smax[h]));
        }
    }
    __syncthreads();
    if (t < H1) srr[t] = __frcp_rn(sden[t] + 1e-16f);
    int c0  = 4 * t;
    int hh0 = c0 / C1, hh1 = (c0 + 1) / C1, hh2 = (c0 + 2) / C1, hh3 = (c0 + 3) / C1;
    float4 acc = make_float4(0.0f, 0.0f, 0.0f, 0.0f);
    for (int j0 = 0; j0 < deg; j0 += CH1) {
        int nc = min(CH1, deg - j0);
        __syncthreads();   // also orders srr before first use
        if (t < nc) csrc[t] = g_ssrc[off + j0 + t];
        if (cached) {
            for (int i = t; i < nc * H1; i += 256) {
                int j = i / H1, h = i - H1 * j;
                cal[j][h] = __expf(ev[j0 + j][h] - smax[h]) * srr[h];
            }
        } else {
            for (int i = t; i < nc * H1; i += 256) {
                int j = i / H1, h = i - H1 * j;
                int s = g_ssrc[off + j0 + j];
                float v = g_as1[s * H1 + h] + sad[h];
                v = v > 0.0f ? v : SLOPE * v;
                cal[j][h] = __expf(v - smax[h]) * srr[h];
            }
        }
        __syncthreads();
        if (t < NV1) {
            for (int j = 0; j < nc; j++) {
                const float4 v = *(const float4*)(g_h1 + (size_t)csrc[j] * F1 + c0);
                acc.x = fmaf(v.x, cal[j][hh0], acc.x);
                acc.y = fmaf(v.y, cal[j][hh1], acc.y);
                acc.z = fmaf(v.z, cal[j][hh2], acc.z);
                acc.w = fmaf(v.w, cal[j][hh3], acc.w);
            }
        }
    }
    if (t < NV1) {
        const float4 bb = *(const float4*)(b1 + c0);
        float4 r;
        float v;
        v = acc.x + bb.x; r.x = v > 0.0f ? v : expm1f(v);
        v = acc.y + bb.y; r.y = v > 0.0f ? v : expm1f(v);
        v = acc.z + bb.z; r.z = v > 0.0f ? v : expm1f(v);
        v = acc.w + bb.w; r.w = v > 0.0f ? v : expm1f(v);
        *(float4*)(g_out1 + (size_t)d * F1 + c0) = r;
    }
}

// ---------------- GEMM2: h2 = out1 @ W2, 100 outs x 64 nodes, k-tiled + prefetch ----------------
#define G2NN 64
#define G2KT 78
#define G2PAD 68
__global__ void __launch_bounds__(256) k_gemm2(const float* __restrict__ W2) {
    __shared__ float xs[G2KT * G2PAD];           // 21.2 KB, layout [k][node]
    int tid = threadIdx.x;                       // 256
    int n0  = blockIdx.x * G2NN;
    int ob  = (tid & 31) * 4;                    // 0..124; active < 100
    int nb  = (tid >> 5) * 8;
    float acc[8][4];
#pragma unroll
    for (int n = 0; n < 8; n++)
#pragma unroll
        for (int q = 0; q < 4; q++) acc[n][q] = 0.0f;
    for (int kt = 0; kt < F1; kt += G2KT) {
        __syncthreads();
        for (int i = tid; i < G2NN * G2KT; i += 256) {
            int nn = i / G2KT, k = i - nn * G2KT;
            int node = n0 + nn;
            xs[k * G2PAD + nn] = (node < NN) ? g_out1[(size_t)node * F1 + kt + k] : 0.0f;
        }
        __syncthreads();
        if (ob < C2) {
            float4 w  = *(const float4*)&W2[(size_t)kt * C2 + ob];
            float4 xa = *(const float4*)&xs[nb];
            float4 xb = *(const float4*)&xs[nb + 4];
            for (int k = 0; k < G2KT; k++) {
                float4 wc = w, xac = xa, xbc = xb;
                if (k + 1 < G2KT) {                // prefetch k+1
                    w  = *(const float4*)&W2[(size_t)(kt + k + 1) * C2 + ob];
                    xa = *(const float4*)&xs[(k + 1) * G2PAD + nb];
                    xb = *(const float4*)&xs[(k + 1) * G2PAD + nb + 4];
                }
                float xv[8] = {xac.x, xac.y, xac.z, xac.w, xbc.x, xbc.y, xbc.z, xbc.w};
#pragma unroll
                for (int n = 0; n < 8; n++) {
                    acc[n][0] = fmaf(xv[n], wc.x, acc[n][0]);
                    acc[n][1] = fmaf(xv[n], wc.y, acc[n][1]);
                    acc[n][2] = fmaf(xv[n], wc.z, acc[n][2]);
                    acc[n][3] = fmaf(xv[n], wc.w, acc[n][3]);
                }
            }
        }
    }
    if (ob < C2) {
#pragma unroll
        for (int n = 0; n < 8; n++) {
            int node = n0 + nb + n;
            if (node < NN)
                *(float4*)&g_h2[(size_t)node * C2 + ob] =
                    make_float4(acc[n][0], acc[n][1], acc[n][2], acc[n][3]);
        }
    }
}

__global__ void k_alpha2(const float* __restrict__ as, const float* __restrict__ ad) {
    int gw   = (blockIdx.x * blockDim.x + threadIdx.x) >> 5;
    int lane = threadIdx.x & 31;
    if (gw < NN) {
        const float* hp = g_h2 + (size_t)gw * C2;
        float s = 0.0f, d = 0.0f;
        for (int k = lane; k < C2; k += 32) {
            float v = hp[k];
            s = fmaf(v, as[k], s);
            d = fmaf(v, ad[k], d);
        }
#pragma unroll
        for (int off = 16; off; off >>= 1) {
            s += __shfl_down_sync(0xffffffffu, s, off);
            d += __shfl_down_sync(0xffffffffu, d, off);
        }
        if (lane == 0) { g_as2[gw] = s; g_ad2[gw] = d; }
    }
}

// ---------------- layer-2 fused softmax + aggregation + bias + ReLU + pool ----------------
#define CH2 32
__global__ void k_agg2(const float* __restrict__ b2) {
    int d = blockIdx.x;
    int t = threadIdx.x;                      // 128
    __shared__ float smax, sden, sad, srr;
    __shared__ int   csrc[CH2];
    __shared__ float cal[CH2];
    if (t == 0) {
        smax = __int_as_float(0xff800000);
        sden = 0.0f;
        sad  = g_ad2[d];
    }
    __syncthreads();
    int off = g_off[d], deg = g_off[d + 1] - off;
    for (int j = t; j < deg; j += 128) {
        float v = g_as2[g_ssrc[off + j]] + sad;
        v = v > 0.0f ? v : SLOPE * v;
        atomicMaxF(&smax, v);
    }
    __syncthreads();
    for (int j = t; j < deg; j += 128) {
        float v = g_as2[g_ssrc[off + j]] + sad;
        v = v > 0.0f ? v : SLOPE * v;
        atomicAdd(&sden, __expf(v - smax));
    }
    __syncthreads();
    if (t == 0) srr = __frcp_rn(sden + 1e-16f);
    float acc = 0.0f;
    for (int j0 = 0; j0 < deg; j0 += CH2) {
        int nc = min(CH2, deg - j0);
        __syncthreads();   // also orders srr before first use
        if (t < nc) {
            int s = g_ssrc[off + j0 + t];
            csrc[t] = s;
            float v = g_as2[s] + sad;
            v = v > 0.0f ? v : SLOPE * v;
            cal[t] = __expf(v - smax) * srr;
        }
        __syncthreads();
        if (t < C2)
            for (int j = 0; j < nc; j++)
                acc = fmaf(g_h2[(size_t)csrc[j] * C2 + t], cal[j], acc);
    }
    if (t < C2) {
        float v = fmaxf(acc + b2[t], 0.0f);
        atomicMaxF(&g_gmax[g_batch[d] * C2 + t], v);
    }
}

// ---------------- final: relu(gmax @ Wg + bg) ----------------
__global__ void k_final(const float* __restrict__ Wg, const float* __restrict__ bg,
                        float* __restrict__ out) {
    __shared__ float gs[C2];
    int g = blockIdx.x;
    for (int i = threadIdx.x; i < C2; i += blockDim.x) gs[i] = g_gmax[g * C2 + i];
    __syncthreads();
    int o = threadIdx.x;
    if (o < C2) {
        float a = 0.0f;
        for (int k = 0; k < C2; k++) a = fmaf(gs[k], Wg[k * C2 + o], a);
        out[g * C2 + o] = fmaxf(a + bg[o], 0.0f);
    }
}

// ---------------- launcher ----------------
extern "C" void kernel_launch(void* const* d_in, const int* in_sizes, int n_in,
                              void* d_out, int out_size) {
    // Input order per setup_inputs(): x, edge_index, batch, [num_graphs],
    // W1, a_src1, a_dst1, b1, W2, a_src2, a_dst2, b2, Wg, bg.
    int sh = (n_in >= 14) ? 1 : 0;   // extra slot for num_graphs scalar
    const float* x      = (const float*)d_in[0];
    const int*   eidx   = (const int*)d_in[1];
    const int*   batch  = (const int*)d_in[2];
    const float* W1     = (const float*)d_in[3 + sh];
    const float* a_src1 = (const float*)d_in[4 + sh];
    const float* a_dst1 = (const float*)d_in[5 + sh];
    const float* b1     = (const float*)d_in[6 + sh];
    const float* W2     = (const float*)d_in[7 + sh];
    const float* a_src2 = (const float*)d_in[8 + sh];
    const float* a_dst2 = (const float*)d_in[9 + sh];
    const float* b2     = (const float*)d_in[10 + sh];
    const float* Wg     = (const float*)d_in[11 + sh];
    const float* bg     = (const float*)d_in[12 + sh];
    float* out = (float*)d_out;

    k_prep<<<1024, 256>>>((const unsigned int*)eidx);
    k_convert<<<1024, 256>>>(eidx, batch);
    k_scan<<<1, 1024>>>();
    // gemm1 stays launch #4 so ncu (-s 5 -c 1) profiles it again for comparison.
    dim3 g1((F1 + G1ON - 1) / G1ON, (NN + G1NN - 1) / G1NN);
    k_gemm1<<<g1, 256>>>(x, W1);
    k_scatter<<<1024, 256>>>();

    k_alpha1<<<(NN * H1 * 32 + 255) / 256, 256>>>(a_src1, a_dst1);
    k_agg1<<<NN, 256>>>(b1);

    k_gemm2<<<(NN + G2NN - 1) / G2NN, 256>>>(W2);
    k_alpha2<<<(NN * 32 + 255) / 256, 256>>>(a_src2, a_dst2);

    k_agg2<<<NN, 128>>>(b2);

    k_final<<<NG, 128>>>(Wg, bg, out);
}

// round 16
// speedup vs baseline: 1.2045x; 1.2045x over previous
#include <cuda_runtime.h>

// ---------------- problem constants ----------------
#define NN     20000        // nodes
#define E0     320000       // input edges
#define EA     340000       // edges + self loops
#define NG     512          // graphs
#define H1     10           // heads layer 1
#define C1     78           // per-head channels layer 1
#define F0     78           // input features
#define F1     780          // H1*C1
#define C2     100          // layer-2 channels
#define SLOPE  0.2f

// ---------------- device scratch (static; no runtime allocation) ----------------
__device__ int   g_is32;
__device__ int   g_src[EA];
__device__ int   g_dst[EA];
__device__ int   g_ssrc[EA];          // src permuted into dst-sorted order (CSR)
__device__ int   g_cnt[NN];
__device__ int   g_cur[NN];
__device__ int   g_off[NN + 1];
__device__ int   g_batch[NN];
__device__ float g_h1[NN * F1];       // 62 MB
__device__ float g_as1[NN * H1];
__device__ float g_ad1[NN * H1];
__device__ float g_out1[NN * F1];     // 62 MB (post bias+ELU)
__device__ float g_h2[NN * C2];
__device__ float g_as2[NN];
__device__ float g_ad2[NN];
__device__ float g_gmax[NG * C2];

// float atomic max via sign-aware integer ops (monotone in float order).
__device__ __forceinline__ void atomicMaxF(float* a, float v) {
    if (v >= 0.0f) atomicMax((int*)a, __float_as_int(v));
    else           atomicMin((unsigned int*)a, __float_as_uint(v));
}

// ---------------- prep: init + int-width detect fused ----------------
__global__ void k_prep(const unsigned int* __restrict__ buf) {
    int i = blockIdx.x * blockDim.x + threadIdx.x;
    int stride = gridDim.x * blockDim.x;
    for (int j = i; j < NN; j += stride) { g_cnt[j] = 0; g_cur[j] = 0; }
    for (int j = i; j < NG * C2; j += stride) g_gmax[j] = 0.0f; // pooled vals post-ReLU >= 0
    if (i == 0) g_is32 = 0;
    int found = 0;
    for (int j = 2 * i + 1; j < 2 * E0; j += 2 * stride) found |= (buf[j] != 0u);
    if (found) atomicOr(&g_is32, 1);   // benign race with init (0 -> or 1)
}

// convert + histogram fused
__global__ void k_convert(const int* __restrict__ eidx, const int* __restrict__ bin) {
    int i = blockIdx.x * blockDim.x + threadIdx.x;
    int stride = gridDim.x * blockDim.x;
    int is32 = g_is32;
    for (int e = i; e < EA; e += stride) {
        int s, d;
        if (e < E0) {
            if (is32) { s = eidx[e];     d = eidx[E0 + e]; }
            else      { s = eidx[2 * e]; d = eidx[2 * E0 + 2 * e]; }
        } else { s = e - E0; d = s; }   // self loop
        g_src[e] = s; g_dst[e] = d;
        atomicAdd(&g_cnt[d], 1);
    }
    for (int n = i; n < NN; n += stride)
        g_batch[n] = is32 ? bin[n] : bin[2 * n];
}

// ---------------- single-pass scan: 1024 threads x 20 elements (int4 loads) ----------------
#define SPER 20   // 1024 * 20 = 20480 >= NN+1
__global__ void k_scan() {
    int t = threadIdx.x;
    int base = t * SPER;                         // 80-byte aligned
    int raw[SPER];
#pragma unroll
    for (int q = 0; q < SPER / 4; q++) {
        int4 v4 = make_int4(0, 0, 0, 0);
        if (base + q * 4 + 3 < NN) v4 = *(const int4*)&g_cnt[base + q * 4];
        else {
#pragma unroll
            for (int r = 0; r < 4; r++) {
                int idx = base + q * 4 + r;
                ((int*)&v4)[r] = (idx < NN) ? g_cnt[idx] : 0;
            }
        }
        raw[q * 4 + 0] = v4.x; raw[q * 4 + 1] = v4.y;
        raw[q * 4 + 2] = v4.z; raw[q * 4 + 3] = v4.w;
    }
    int vals[SPER];
    int sum = 0;
#pragma unroll
    for (int i = 0; i < SPER; i++) { vals[i] = sum; sum += raw[i]; }
    __shared__ int wsum[32];
    int x = sum;
#pragma unroll
    for (int o = 1; o < 32; o <<= 1) {
        int y = __shfl_up_sync(0xffffffffu, x, o);
        if ((t & 31) >= o) x += y;
    }
    if ((t & 31) == 31) wsum[t >> 5] = x;
    __syncthreads();
    if (t < 32) {
        int w = wsum[t];
#pragma unroll
        for (int o = 1; o < 32; o <<= 1) {
            int y = __shfl_up_sync(0xffffffffu, w, o);
            if (t >= o) w += y;
        }
        wsum[t] = w;
    }
    __syncthreads();
    int prev = (x - sum) + ((t >= 32) ? wsum[(t >> 5) - 1] : 0);
#pragma unroll
    for (int i = 0; i < SPER; i++) {
        int idx = base + i;
        if (idx <= NN) g_off[idx] = prev + vals[i];
    }
}

__global__ void k_scatter() {
    int i = blockIdx.x * blockDim.x + threadIdx.x;
    int stride = gridDim.x * blockDim.x;
    for (int e = i; e < EA; e += stride) {
        int d = g_dst[e];
        int pos = g_off[d] + atomicAdd(&g_cur[d], 1);
        g_ssrc[pos] = g_src[e];
    }
}

// ---------------- GEMM1: h1 = x @ W1, register-tiled 128 outs x 64 nodes (R7, measured 104us) --
#define G1ON 128
#define G1NN 64
#define G1PAD 68     // padded node stride (16B-aligned)
__global__ void k_gemm1(const float* __restrict__ x, const float* __restrict__ W1) {
    __shared__ float xs[F0 * G1PAD];             // 21.2 KB, layout [k][node]
    int tid = threadIdx.x;                       // 256
    int n0  = blockIdx.y * G1NN;
    int ob  = blockIdx.x * G1ON + (tid & 31) * 4;
    int nb  = (tid >> 5) * 8;
    for (int i = tid; i < G1NN * F0; i += 256) {
        int nn = i / F0, k = i - nn * F0;
        int node = n0 + nn;
        xs[k * G1PAD + nn] = (node < NN) ? x[(size_t)node * F0 + k] : 0.0f;
    }
    __syncthreads();
    float acc[8][4];
#pragma unroll
    for (int n = 0; n < 8; n++)
#pragma unroll
        for (int q = 0; q < 4; q++) acc[n][q] = 0.0f;
    if (ob < F1) {
        for (int k = 0; k < F0; k++) {
            float4 w = *(const float4*)&W1[k * F1 + ob];
            const float* xr = &xs[k * G1PAD + nb];
            float4 xa = *(const float4*)xr;
            float4 xb = *(const float4*)(xr + 4);
            float xv[8] = {xa.x, xa.y, xa.z, xa.w, xb.x, xb.y, xb.z, xb.w};
#pragma unroll
            for (int n = 0; n < 8; n++) {
                acc[n][0] = fmaf(xv[n], w.x, acc[n][0]);
                acc[n][1] = fmaf(xv[n], w.y, acc[n][1]);
                acc[n][2] = fmaf(xv[n], w.z, acc[n][2]);
                acc[n][3] = fmaf(xv[n], w.w, acc[n][3]);
            }
        }
#pragma unroll
        for (int n = 0; n < 8; n++) {
            int node = n0 + nb + n;
            if (node < NN)
                *(float4*)&g_h1[(size_t)node * F1 + ob] =
                    make_float4(acc[n][0], acc[n][1], acc[n][2], acc[n][3]);
        }
    }
}

// alpha_{s,d}1[n][h] = dot(h1[n, h*C1:], a_{src,dst}1[h]) — one warp per (n,h)
__global__ void k_alpha1(const float* __restrict__ as, const float* __restrict__ ad) {
    int gw   = (blockIdx.x * blockDim.x + threadIdx.x) >> 5;
    int lane = threadIdx.x & 31;
    if (gw < NN * H1) {
        int n = gw / H1, h = gw - n * H1;
        const float* hp = g_h1 + (size_t)n * F1 + h * C1;
        float s = 0.0f, d = 0.0f;
        for (int k = lane; k < C1; k += 32) {
            float v = hp[k];
            s = fmaf(v, as[h * C1 + k], s);
            d = fmaf(v, ad[h * C1 + k], d);
        }
#pragma unroll
        for (int off = 16; off; off >>= 1) {
            s += __shfl_down_sync(0xffffffffu, s, off);
            d += __shfl_down_sync(0xffffffffu, d, off);
        }
        if (lane == 0) { g_as1[gw] = s; g_ad1[gw] = d; }
    }
}

// ---------------- layer-1 fused softmax + aggregation (R6 version, one block per dst) --------
#define CH1 16
#define NV1 195          // F1/4 float4 lanes
__global__ void k_agg1(const float* __restrict__ b1) {
    int d = blockIdx.x;
    int t = threadIdx.x;                      // 256
    __shared__ float smax[H1], sden[H1], sad[H1], srr[H1];
    __shared__ int   csrc[CH1];
    __shared__ float cal[CH1][H1];
    if (t < H1) {
        smax[t] = __int_as_float(0xff800000); // -inf
        sden[t] = 0.0f;
        sad[t]  = g_ad1[d * H1 + t];
    }
    __syncthreads();
    int off = g_off[d], deg = g_off[d + 1] - off;
    int n = deg * H1;
    // pass 1: per-head max of leaky_relu(as[src]+ad[dst])
    for (int i = t; i < n; i += 256) {
        int j = i / H1, h = i - H1 * j;
        int s = g_ssrc[off + j];
        float v = g_as1[s * H1 + h] + sad[h];
        v = v > 0.0f ? v : SLOPE * v;
        atomicMaxF(&smax[h], v);
    }
    __syncthreads();
    // pass 2: per-head denominator
    for (int i = t; i < n; i += 256) {
        int j = i / H1, h = i - H1 * j;
        int s = g_ssrc[off + j];
        float v = g_as1[s * H1 + h] + sad[h];
        v = v > 0.0f ? v : SLOPE * v;
        atomicAdd(&sden[h], __expf(v - smax[h]));
    }
    __syncthreads();
    if (t < H1) srr[t] = __frcp_rn(sden[t] + 1e-16f);
    // pass 3: chunked aggregate, alpha inline, float4 channels per thread
    int c0  = 4 * t;
    int hh0 = c0 / C1, hh1 = (c0 + 1) / C1, hh2 = (c0 + 2) / C1, hh3 = (c0 + 3) / C1;
    float4 acc = make_float4(0.0f, 0.0f, 0.0f, 0.0f);
    for (int j0 = 0; j0 < deg; j0 += CH1) {
        int nc = min(CH1, deg - j0);
        __syncthreads();   // also orders srr before first use
        if (t < nc) csrc[t] = g_ssrc[off + j0 + t];
        for (int i = t; i < nc * H1; i += 256) {
            int j = i / H1, h = i - H1 * j;
            int s = g_ssrc[off + j0 + j];
            float v = g_as1[s * H1 + h] + sad[h];
            v = v > 0.0f ? v : SLOPE * v;
            cal[j][h] = __expf(v - smax[h]) * srr[h];
        }
        __syncthreads();
        if (t < NV1) {
            for (int j = 0; j < nc; j++) {
                const float4 v = *(const float4*)(g_h1 + (size_t)csrc[j] * F1 + c0);
                acc.x = fmaf(v.x, cal[j][hh0], acc.x);
                acc.y = fmaf(v.y, cal[j][hh1], acc.y);
                acc.z = fmaf(v.z, cal[j][hh2], acc.z);
                acc.w = fmaf(v.w, cal[j][hh3], acc.w);
            }
        }
    }
    if (t < NV1) {
        const float4 bb = *(const float4*)(b1 + c0);
        float4 r;
        float v;
        v = acc.x + bb.x; r.x = v > 0.0f ? v : expm1f(v);
        v = acc.y + bb.y; r.y = v > 0.0f ? v : expm1f(v);
        v = acc.z + bb.z; r.z = v > 0.0f ? v : expm1f(v);
        v = acc.w + bb.w; r.w = v > 0.0f ? v : expm1f(v);
        *(float4*)(g_out1 + (size_t)d * F1 + c0) = r;
    }
}

// ---------------- GEMM2: h2 = out1 @ W2, register-tiled 6 nodes x 4 outs (R6 version) --------
#define GTN 48          // nodes per block
#define GKT 130         // k-tile
__global__ void k_gemm2(const float* __restrict__ W2) {
    __shared__ float xs[GTN * GKT];           // 24.4 KB
    int n0  = blockIdx.x * GTN;
    int tid = threadIdx.x;                    // 256
    int ob  = (tid & 31) * 4;                 // output base (0..124; active < 100)
    int nb  = (tid >> 5) * 6;                 // node base within tile (8 groups x 6)
    float acc[6][4];
#pragma unroll
    for (int n = 0; n < 6; n++)
#pragma unroll
        for (int q = 0; q < 4; q++) acc[n][q] = 0.0f;
    for (int kt = 0; kt < F1; kt += GKT) {
        for (int i = tid; i < GTN * GKT; i += 256) {
            int nn = i / GKT, k = i - nn * GKT;
            int node = n0 + nn;
            xs[i] = (node < NN) ? g_out1[(size_t)node * F1 + kt + k] : 0.0f;
        }
        __syncthreads();
        if (ob < C2) {
            for (int k = 0; k < GKT; k++) {
                float4 w = *(const float4*)&W2[(kt + k) * C2 + ob];
#pragma unroll
                for (int n = 0; n < 6; n++) {
                    float xv = xs[(nb + n) * GKT + k];
                    acc[n][0] = fmaf(xv, w.x, acc[n][0]);
                    acc[n][1] = fmaf(xv, w.y, acc[n][1]);
                    acc[n][2] = fmaf(xv, w.z, acc[n][2]);
                    acc[n][3] = fmaf(xv, w.w, acc[n][3]);
                }
            }
        }
        __syncthreads();
    }
    if (ob < C2) {
#pragma unroll
        for (int n = 0; n < 6; n++) {
            int node = n0 + nb + n;
            if (node < NN) {
                float4 r = make_float4(acc[n][0], acc[n][1], acc[n][2], acc[n][3]);
                *(float4*)&g_h2[(size_t)node * C2 + ob] = r;
            }
        }
    }
}

__global__ void k_alpha2(const float* __restrict__ as, const float* __restrict__ ad) {
    int gw   = (blockIdx.x * blockDim.x + threadIdx.x) >> 5;
    int lane = threadIdx.x & 31;
    if (gw < NN) {
        const float* hp = g_h2 + (size_t)gw * C2;
        float s = 0.0f, d = 0.0f;
        for (int k = lane; k < C2; k += 32) {
            float v = hp[k];
            s = fmaf(v, as[k], s);
            d = fmaf(v, ad[k], d);
        }
#pragma unroll
        for (int off = 16; off; off >>= 1) {
            s += __shfl_down_sync(0xffffffffu, s, off);
            d += __shfl_down_sync(0xffffffffu, d, off);
        }
        if (lane == 0) { g_as2[gw] = s; g_ad2[gw] = d; }
    }
}

// ---------------- layer-2 fused softmax + aggregation + bias + ReLU + pool ----------------
#define CH2 32
__global__ void k_agg2(const float* __restrict__ b2) {
    int d = blockIdx.x;
    int t = threadIdx.x;                      // 128
    __shared__ float smax, sden, sad, srr;
    __shared__ int   csrc[CH2];
    __shared__ float cal[CH2];
    if (t == 0) {
        smax = __int_as_float(0xff800000);
        sden = 0.0f;
        sad  = g_ad2[d];
    }
    __syncthreads();
    int off = g_off[d], deg = g_off[d + 1] - off;
    for (int j = t; j < deg; j += 128) {
        float v = g_as2[g_ssrc[off + j]] + sad;
        v = v > 0.0f ? v : SLOPE * v;
        atomicMaxF(&smax, v);
    }
    __syncthreads();
    for (int j = t; j < deg; j += 128) {
        float v = g_as2[g_ssrc[off + j]] + sad;
        v = v > 0.0f ? v : SLOPE * v;
        atomicAdd(&sden, __expf(v - smax));
    }
    __syncthreads();
    if (t == 0) srr = __frcp_rn(sden + 1e-16f);
    float acc = 0.0f;
    for (int j0 = 0; j0 < deg; j0 += CH2) {
        int nc = min(CH2, deg - j0);
        __syncthreads();   // also orders srr before first use
        if (t < nc) {
            int s = g_ssrc[off + j0 + t];
            csrc[t] = s;
            float v = g_as2[s] + sad;
            v = v > 0.0f ? v : SLOPE * v;
            cal[t] = __expf(v - smax) * srr;
        }
        __syncthreads();
        if (t < C2)
            for (int j = 0; j < nc; j++)
                acc = fmaf(g_h2[(size_t)csrc[j] * C2 + t], cal[j], acc);
    }
    if (t < C2) {
        float v = fmaxf(acc + b2[t], 0.0f);
        atomicMaxF(&g_gmax[g_batch[d] * C2 + t], v);
    }
}

// ---------------- final: relu(gmax @ Wg + bg) ----------------
__global__ void k_final(const float* __restrict__ Wg, const float* __restrict__ bg,
                        float* __restrict__ out) {
    __shared__ float gs[C2];
    int g = blockIdx.x;
    for (int i = threadIdx.x; i < C2; i += blockDim.x) gs[i] = g_gmax[g * C2 + i];
    __syncthreads();
    int o = threadIdx.x;
    if (o < C2) {
        float a = 0.0f;
        for (int k = 0; k < C2; k++) a = fmaf(gs[k], Wg[k * C2 + o], a);
        out[g * C2 + o] = fmaxf(a + bg[o], 0.0f);
    }
}

// ---------------- launcher ----------------
extern "C" void kernel_launch(void* const* d_in, const int* in_sizes, int n_in,
                              void* d_out, int out_size) {
    // Input order per setup_inputs(): x, edge_index, batch, [num_graphs],
    // W1, a_src1, a_dst1, b1, W2, a_src2, a_dst2, b2, Wg, bg.
    int sh = (n_in >= 14) ? 1 : 0;   // extra slot for num_graphs scalar
    const float* x      = (const float*)d_in[0];
    const int*   eidx   = (const int*)d_in[1];
    const int*   batch  = (const int*)d_in[2];
    const float* W1     = (const float*)d_in[3 + sh];
    const float* a_src1 = (const float*)d_in[4 + sh];
    const float* a_dst1 = (const float*)d_in[5 + sh];
    const float* b1     = (const float*)d_in[6 + sh];
    const float* W2     = (const float*)d_in[7 + sh];
    const float* a_src2 = (const float*)d_in[8 + sh];
    const float* a_dst2 = (const float*)d_in[9 + sh];
    const float* b2     = (const float*)d_in[10 + sh];
    const float* Wg     = (const float*)d_in[11 + sh];
    const float* bg     = (const float*)d_in[12 + sh];
    float* out = (float*)d_out;

    k_prep<<<1024, 256>>>((const unsigned int*)eidx);
    k_convert<<<1024, 256>>>(eidx, batch);
    k_scan<<<1, 1024>>>();
    // gemm1 stays launch #4 so ncu (-s 5 -c 1) keeps profiling it.
    dim3 g1((F1 + G1ON - 1) / G1ON, (NN + G1NN - 1) / G1NN);
    k_gemm1<<<g1, 256>>>(x, W1);
    k_scatter<<<1024, 256>>>();

    k_alpha1<<<(NN * H1 * 32 + 255) / 256, 256>>>(a_src1, a_dst1);
    k_agg1<<<NN, 256>>>(b1);

    k_gemm2<<<(NN + GTN - 1) / GTN, 256>>>(W2);
    k_alpha2<<<(NN * 32 + 255) / 256, 256>>>(a_src2, a_dst2);

    k_agg2<<<NN, 128>>>(b2);

    k_final<<<NG, 128>>>(Wg, bg, out);
}